// round 5
// baseline (speedup 1.0000x reference)
#include <cuda_runtime.h>
#include <cuda_bf16.h>
#include <math.h>

// B=16, T=32 (early exit: only token 31 used; all ops causal), DM=256,
// DI=512, DS=16, DR=16, DCONV=4, L=4.
// One persistent kernel; 16 clusters (one per batch) x 8 CTAs; all syncs are
// cluster-local (no cross-batch dependency exists after featurize).

#define NB      16
#define TT      32
#define NTOK    (NB*TT)      // 512
#define DM      256
#define DI      512
#define DS      16
#define DR      16
#define NL      4
#define THREADS 256
#define CSZ     8            // CTAs per cluster

// scratch (device globals; no allocation allowed) — 16B aligned for float4
__device__ __align__(16) float g_feat[NTOK*DM];
__device__ __align__(16) float g_xz  [NTOK*2*DI];
__device__ __align__(16) float g_dbl [NTOK*48];
__device__ __align__(16) float g_xct [NB*DI*TT];
__device__ __align__(16) float g_ztr [NB*DI*TT];
__device__ __align__(16) float g_dtt [NB*DI*TT];
__device__ __align__(16) float g_y   [NTOK*DI];
__device__ __align__(16) float g_outp[2][NTOK*DM];

__device__ __forceinline__ void csync() {
    asm volatile("barrier.cluster.arrive.aligned;" ::: "memory");
    asm volatile("barrier.cluster.wait.aligned;"   ::: "memory");
}

#define SMTOT 5440   // floats; max stage = in_proj gemm (1152 + 4224)

__global__ void __cluster_dims__(CSZ, 1, 1) __launch_bounds__(THREADS)
mega(const float* __restrict__ x,
     const float* __restrict__ ep,  const float* __restrict__ ef,
     const float* __restrict__ ed,
     const float* __restrict__ plw, const float* __restrict__ plb,
     const float* __restrict__ piw, const float* __restrict__ pib,
     const float* __restrict__ fw,  const float* __restrict__ fb,
     const float* __restrict__ tg,  const float* __restrict__ tb,
     const float* __restrict__ ng,  const float* __restrict__ nb,
     const float* __restrict__ ipw, const float* __restrict__ cw,
     const float* __restrict__ cb,  const float* __restrict__ xpw,
     const float* __restrict__ dtw, const float* __restrict__ dtb,
     const float* __restrict__ alog,const float* __restrict__ dp,
     const float* __restrict__ opw,
     const float* __restrict__ w1,  const float* __restrict__ b1,
     const float* __restrict__ w2,  const float* __restrict__ b2,
     float* __restrict__ out)
{
    __shared__ __align__(16) float SMF[SMTOT];
    const int tid  = threadIdx.x;
    const int b    = blockIdx.x >> 3;    // batch (cluster id)
    const int rank = blockIdx.x & 7;     // CTA rank within cluster

    // ---------------- featurize + tok LN (4 tokens per rank) -------------
    {
        float* cat = SMF;          // 136
        float* red = SMF + 144;    // 256
        for (int ti = 0; ti < 4; ti++) {
            int tl  = rank*4 + ti;
            int tok = b*TT + tl;
            const float* xr = x + (b*1024 + tl)*5;
            int d = tid;
            if (d < 136) {
                float v;
                if (d < 32)       { int p=(int)xr[0]; p=min(max(p,0),255); v=ep[p*32+d]; }
                else if (d < 64)  { v = xr[1]*plw[d-32] + plb[d-32]; }
                else if (d < 96)  { int f=(int)xr[2]; f=min(max(f,0),63); v=ef[f*32+(d-64)]; }
                else if (d < 128) { v = xr[3]*piw[d-96] + pib[d-96]; }
                else              { int dd=(int)xr[4]; dd=min(max(dd,0),1); v=ed[dd*8+(d-128)]; }
                cat[d] = v;
            }
            __syncthreads();
            float acc = fb[d];
            const float* wrow = fw + d*136;
            #pragma unroll 8
            for (int j = 0; j < 136; j++) acc += cat[j]*wrow[j];
            red[d] = acc; __syncthreads();
            for (int off=128; off; off>>=1){ if (d<off) red[d]+=red[d+off]; __syncthreads(); }
            float mean = red[0]*(1.f/DM); __syncthreads();
            float dv = acc-mean; red[d]=dv*dv; __syncthreads();
            for (int off=128; off; off>>=1){ if (d<off) red[d]+=red[d+off]; __syncthreads(); }
            float var = red[0]*(1.f/DM);
            g_feat[tok*DM + d] = dv*rsqrtf(var+1e-5f)*tg[d] + tb[d];
            __syncthreads();
        }
    }
    csync();

    for (int l = 0; l < NL; l++) {
        const float* ipw_l = ipw + (size_t)l*2*DI*DM;
        const float* cw_l  = cw  + (size_t)l*DI*4;
        const float* cb_l  = cb  + (size_t)l*DI;
        const float* xpw_l = xpw + (size_t)l*48*DI;
        const float* dtw_l = dtw + (size_t)l*DI*DR;
        const float* dtb_l = dtb + (size_t)l*DI;
        const float* al_l  = alog+ (size_t)l*DI*DS;
        const float* dp_l  = dp  + (size_t)l*DI;
        const float* opw_l = opw + (size_t)l*DM*DI;

        // -------- in_proj: xz[32,1024] = feat[32,256] @ W^T --------------
        // each rank: 128-col slice, full K=256, BK=32, 4x4 microtile
        {
            float (*As)[36]  = (float(*)[36])SMF;            // 32x36 (stride mult of 4)
            float (*Bs)[132] = (float(*)[132])(SMF + 1152);  // 32x132
            const int nb0 = rank*128;
            const float* A = g_feat + (size_t)b*TT*DM;
            int ty = tid >> 5, tx = tid & 31;
            float acc[4][4] = {};
            for (int k0 = 0; k0 < DM; k0 += 32) {
                {   // A: 32x32 = 256 float4, one per thread
                    int m = tid >> 3, kq = (tid & 7)*4;
                    float4 av = *(const float4*)(A + (size_t)m*DM + k0 + kq);
                    As[kq+0][m]=av.x; As[kq+1][m]=av.y; As[kq+2][m]=av.z; As[kq+3][m]=av.w;
                }
                #pragma unroll
                for (int j = 0; j < 4; j++) {   // B: 128x32 = 1024 float4
                    int i = tid + j*256;
                    int n = i >> 3, kq = (i & 7)*4;
                    float4 bv = *(const float4*)(ipw_l + (size_t)(nb0+n)*DM + k0 + kq);
                    Bs[kq+0][n]=bv.x; Bs[kq+1][n]=bv.y; Bs[kq+2][n]=bv.z; Bs[kq+3][n]=bv.w;
                }
                __syncthreads();
                #pragma unroll
                for (int k = 0; k < 32; k++) {
                    float4 a  = *(const float4*)&As[k][ty*4];
                    float4 bb = *(const float4*)&Bs[k][tx*4];
                    float ar[4] = {a.x,a.y,a.z,a.w};
                    float br[4] = {bb.x,bb.y,bb.z,bb.w};
                    #pragma unroll
                    for (int r = 0; r < 4; r++)
                        #pragma unroll
                        for (int c = 0; c < 4; c++)
                            acc[r][c] += ar[r]*br[c];
                }
                __syncthreads();
            }
            #pragma unroll
            for (int r = 0; r < 4; r++)
                *(float4*)(g_xz + (size_t)(b*TT + ty*4 + r)*(2*DI) + nb0 + tx*4) =
                    make_float4(acc[r][0],acc[r][1],acc[r][2],acc[r][3]);
        }
        csync();

        // -------- conv+SiLU, x_proj, dt (4 tokens per rank) --------------
        {
            float* xcs  = SMF;        // 512
            float* dbls = SMF + 512;  // 48
            for (int ti = 0; ti < 4; ti++) {
                int tl  = rank*4 + ti;
                int tok = b*TT + tl;
                #pragma unroll
                for (int r = 0; r < 2; r++) {
                    int d = tid + r*256;
                    float acc = cb_l[d];
                    #pragma unroll
                    for (int k = 0; k < 4; k++) {
                        int tt = tl - 3 + k;
                        if (tt >= 0)
                            acc += cw_l[d*4+k] * g_xz[(size_t)(tok-3+k)*(2*DI) + d];
                    }
                    xcs[d] = acc / (1.f + __expf(-acc));
                }
                __syncthreads();
                int warp = tid >> 5, lane = tid & 31;
                #pragma unroll
                for (int i = 0; i < 6; i++) {
                    int o = warp*6 + i;
                    const float* wr = xpw_l + o*DI;
                    float p = 0.f;
                    #pragma unroll
                    for (int j = 0; j < 16; j++) p += xcs[j*32+lane]*wr[j*32+lane];
                    #pragma unroll
                    for (int off = 16; off; off >>= 1)
                        p += __shfl_down_sync(0xffffffffu, p, off);
                    if (lane == 0) { dbls[o] = p; g_dbl[tok*48 + o] = p; }
                }
                __syncthreads();
                #pragma unroll
                for (int r = 0; r < 2; r++) {
                    int d = tid + r*256;
                    float v = dtb_l[d];
                    const float* dwr = dtw_l + d*DR;
                    #pragma unroll
                    for (int rr = 0; rr < DR; rr++) v += dbls[rr]*dwr[rr];
                    int tri = (b*DI + d)*TT + tl;
                    g_dtt[tri] = (v > 20.f) ? v : log1pf(__expf(v));
                    g_xct[tri] = xcs[d];
                    g_ztr[tri] = g_xz[(size_t)tok*(2*DI) + DI + d];
                }
                __syncthreads();
            }
        }
        csync();

        // -------- selective scan: 64 channels per rank -------------------
        {
            float* Bsm = SMF;            // 512
            float* Csm = SMF + 512;      // 512
            float* dts = SMF + 1024;     // 512
            float* ws  = SMF + 1536;     // 512
            float* xs  = SMF + 2048;     // 512
            float* zs  = SMF + 2560;     // 512
            float* es  = SMF + 3072;     // 512
            float* A0s = SMF + 3584;     // 16
            #pragma unroll
            for (int i = tid; i < 512; i += 256) {
                int t = i >> 4, n = i & 15;
                const float* row = g_dbl + (size_t)(b*TT + t)*48;
                Bsm[i] = row[16+n];
                Csm[i] = row[32+n];
            }
            for (int c = 0; c < 4; c++) {
                int ch0 = rank*64 + c*16;
                __syncthreads();
                if (tid < 16) A0s[tid] = -__expf(al_l[(ch0+tid)*DS]);
                __syncthreads();
                #pragma unroll
                for (int i = tid; i < 512; i += 256) {
                    int ch = i >> 5, t2 = i & 31;
                    int tri = (b*DI + ch0 + ch)*TT + t2;
                    float dtv = g_dtt[tri];
                    float xv  = g_xct[tri];
                    dts[ch*32+t2] = dtv;
                    ws [ch*32+t2] = dtv*xv;
                    xs [ch*32+t2] = xv;
                    zs [ch*32+t2] = g_ztr[tri];
                    es [ch*32+t2] = __expf(dtv * A0s[ch]);
                }
                __syncthreads();
                int ch_l = tid >> 4, n = tid & 15;
                int d = ch0 + ch_l;
                float An = -__expf(al_l[d*DS + n]);
                float A0 = A0s[ch_l];
                bool fast = fabsf(An - (float)(n+1)*A0) <= 1e-5f*fabsf(An) + 1e-7f;
                fast = __all_sync(0xffffffffu, fast);
                float Dd = dp_l[d];
                float h = 0.f;
                int np = n + 1;
                if (fast) {
                    #pragma unroll 4
                    for (int t = 0; t < TT; t++) {
                        float e1 = es[ch_l*32+t];
                        float p2 = e1*e1, p4 = p2*p2, p8 = p4*p4;
                        float a = 1.f;
                        if (np & 1)  a *= e1;
                        if (np & 2)  a *= p2;
                        if (np & 4)  a *= p4;
                        if (np & 8)  a *= p8;
                        if (np & 16) a *= p8*p8;
                        h = a*h + ws[ch_l*32+t]*Bsm[t*16+n];
                        float v = h*Csm[t*16+n];
                        v += __shfl_xor_sync(0xffffffffu, v, 8);
                        v += __shfl_xor_sync(0xffffffffu, v, 4);
                        v += __shfl_xor_sync(0xffffffffu, v, 2);
                        v += __shfl_xor_sync(0xffffffffu, v, 1);
                        if (n == 0) {
                            float zv = zs[ch_l*32+t];
                            float sz = zv / (1.f + __expf(-zv));
                            g_y[(size_t)(b*TT+t)*DI + d] = (v + Dd*xs[ch_l*32+t]) * sz;
                        }
                    }
                } else {
                    #pragma unroll 4
                    for (int t = 0; t < TT; t++) {
                        float a = __expf(dts[ch_l*32+t]*An);
                        h = a*h + ws[ch_l*32+t]*Bsm[t*16+n];
                        float v = h*Csm[t*16+n];
                        v += __shfl_xor_sync(0xffffffffu, v, 8);
                        v += __shfl_xor_sync(0xffffffffu, v, 4);
                        v += __shfl_xor_sync(0xffffffffu, v, 2);
                        v += __shfl_xor_sync(0xffffffffu, v, 1);
                        if (n == 0) {
                            float zv = zs[ch_l*32+t];
                            float sz = zv / (1.f + __expf(-zv));
                            g_y[(size_t)(b*TT+t)*DI + d] = (v + Dd*xs[ch_l*32+t]) * sz;
                        }
                    }
                }
            }
        }
        csync();

        // -------- out_proj: rank -> (64-col slice, half-K) partials ------
        {
            float (*As)[36] = (float(*)[36])SMF;            // 32x36
            float (*Bs)[68] = (float(*)[68])(SMF + 1152);   // 32x68
            const int nsl = (rank & 3)*64;
            const int kh  = rank >> 2;           // 0/1 -> K half
            const int kb  = kh*256;
            int ty = tid >> 5, tx = tid & 31;
            float acc[4][2] = {};
            for (int k0 = 0; k0 < 256; k0 += 32) {
                {   // A: y rows 32 x 32k
                    int m = tid >> 3, kq = (tid & 7)*4;
                    float4 av = *(const float4*)(g_y + (size_t)(b*TT+m)*DI + kb + k0 + kq);
                    As[kq+0][m]=av.x; As[kq+1][m]=av.y; As[kq+2][m]=av.z; As[kq+3][m]=av.w;
                }
                #pragma unroll
                for (int j = 0; j < 2; j++) {   // B: 64x32
                    int i = tid + j*256;
                    int n = i >> 3, kq = (i & 7)*4;
                    float4 bv = *(const float4*)(opw_l + (size_t)(nsl+n)*DI + kb + k0 + kq);
                    Bs[kq+0][n]=bv.x; Bs[kq+1][n]=bv.y; Bs[kq+2][n]=bv.z; Bs[kq+3][n]=bv.w;
                }
                __syncthreads();
                #pragma unroll
                for (int k = 0; k < 32; k++) {
                    float4 a  = *(const float4*)&As[k][ty*4];
                    float2 bb = *(const float2*)&Bs[k][tx*2];
                    float ar[4] = {a.x,a.y,a.z,a.w};
                    #pragma unroll
                    for (int r = 0; r < 4; r++) {
                        acc[r][0] += ar[r]*bb.x;
                        acc[r][1] += ar[r]*bb.y;
                    }
                }
                __syncthreads();
            }
            #pragma unroll
            for (int r = 0; r < 4; r++)
                *(float2*)(&g_outp[kh][(size_t)(b*TT + ty*4 + r)*DM + nsl + tx*2]) =
                    make_float2(acc[r][0], acc[r][1]);
        }
        csync();

        // -------- residual + LN -> feat (4 tokens per rank) --------------
        {
            float* red = SMF;
            for (int ti = 0; ti < 4; ti++) {
                int tok = b*TT + rank*4 + ti;
                int d = tid;
                size_t o = (size_t)tok*DM + d;
                float v = g_feat[o] + g_outp[0][o] + g_outp[1][o];
                red[d] = v; __syncthreads();
                for (int off=128; off; off>>=1){ if (d<off) red[d]+=red[d+off]; __syncthreads(); }
                float mean = red[0]*(1.f/DM); __syncthreads();
                float dv = v-mean; red[d]=dv*dv; __syncthreads();
                for (int off=128; off; off>>=1){ if (d<off) red[d]+=red[d+off]; __syncthreads(); }
                float var = red[0]*(1.f/DM);
                g_feat[o] = dv*rsqrtf(var+1e-5f)*ng[d] + nb[d];
                __syncthreads();
            }
        }
        csync();
    }

    // ---------------- classifier on token 31 (rank 0 per cluster) ---------
    if (rank == 0) {
        float* hs = SMF;
        int j = tid;
        const float* fr = g_feat + (size_t)(b*TT + 31)*DM;
        if (j < 128) {
            float acc = b1[j];
            const float* wr = w1 + j*DM;
            #pragma unroll 8
            for (int d = 0; d < DM; d++) acc += fr[d]*wr[d];
            hs[j] = fmaxf(acc, 0.f);
        }
        __syncthreads();
        if (j < 2) {
            float o = b2[j];
            const float* w2r = w2 + j*128;
            #pragma unroll 8
            for (int k = 0; k < 128; k++) o += hs[k]*w2r[k];
            out[b*2 + j] = o;
        }
    }
}

// ---------------------------------------------------------------------------
extern "C" void kernel_launch(void* const* d_in, const int* in_sizes, int n_in,
                              void* d_out, int out_size)
{
    mega<<<NB*CSZ, THREADS>>>(
        (const float*)d_in[0],  (const float*)d_in[1],  (const float*)d_in[2],
        (const float*)d_in[3],  (const float*)d_in[4],  (const float*)d_in[5],
        (const float*)d_in[6],  (const float*)d_in[7],  (const float*)d_in[8],
        (const float*)d_in[9],  (const float*)d_in[10], (const float*)d_in[11],
        (const float*)d_in[12], (const float*)d_in[13], (const float*)d_in[14],
        (const float*)d_in[15], (const float*)d_in[16], (const float*)d_in[17],
        (const float*)d_in[18], (const float*)d_in[19], (const float*)d_in[20],
        (const float*)d_in[21], (const float*)d_in[22], (const float*)d_in[23],
        (const float*)d_in[24], (const float*)d_in[25], (const float*)d_in[26],
        (float*)d_out);
}

// round 6
// speedup vs baseline: 1.2862x; 1.2862x over previous
#include <cuda_runtime.h>
#include <cuda_bf16.h>
#include <math.h>

// B=16, T=32 (early exit: only token 31 used; all ops causal), DM=256,
// DI=512, DS=16, DR=16, DCONV=4, L=4.
// One persistent kernel; 16 batch-groups x 8 CTAs; per-batch global spin
// barriers (no L1 flush); cross-CTA activation reads via __ldcg.

#define NB      16
#define TT      32
#define NTOK    (NB*TT)      // 512
#define DM      256
#define DI      512
#define DS      16
#define DR      16
#define NL      4
#define THREADS 256
#define CSZ     8            // CTAs per batch group
#define BSTRIDE 32           // counter padding (128B)

// scratch (device globals; no allocation allowed) — 16B aligned for float4
__device__ __align__(16) float g_feat[NTOK*DM];
__device__ __align__(16) float g_xz  [NTOK*2*DI];
__device__ __align__(16) float g_dbl [NTOK*48];
__device__ __align__(16) float g_xct [NB*DI*TT];
__device__ __align__(16) float g_ztr [NB*DI*TT];
__device__ __align__(16) float g_dtt [NB*DI*TT];
__device__ __align__(16) float g_y   [NTOK*DI];
__device__ __align__(16) float g_outp[2][NTOK*DM];

__device__ unsigned g_cnt[NB*BSTRIDE];   // zero-init; self-resetting
__device__ unsigned g_fin[NB*BSTRIDE];

// per-batch spin barrier: monotonic arrival count, target advances by CSZ
__device__ __forceinline__ void bsync(int b, unsigned& target) {
    __syncthreads();
    if (threadIdx.x == 0) {
        target += CSZ;
        __threadfence();
        atomicAdd(&g_cnt[b*BSTRIDE], 1u);
        while (atomicAdd(&g_cnt[b*BSTRIDE], 0u) < target) { }
        __threadfence();
    }
    __syncthreads();
}

// ---- packed dual-fp32 helpers (Blackwell f32x2) ---------------------------
__device__ __forceinline__ unsigned long long pk2(float lo, float hi) {
    unsigned long long r;
    asm("mov.b64 %0, {%1, %2};" : "=l"(r) : "f"(lo), "f"(hi));
    return r;
}
__device__ __forceinline__ void fma2(unsigned long long& d,
                                     unsigned long long a, unsigned long long b) {
    asm("fma.rn.f32x2 %0, %1, %2, %0;" : "+l"(d) : "l"(a), "l"(b));
}
__device__ __forceinline__ float2 upk2(unsigned long long v) {
    float2 f;
    asm("mov.b64 {%0, %1}, %2;" : "=f"(f.x), "=f"(f.y) : "l"(v));
    return f;
}

#define SMTOT 5440   // floats; max stage = in_proj gemm (1152 + 4224)

__global__ void __launch_bounds__(THREADS)
mega(const float* __restrict__ x,
     const float* __restrict__ ep,  const float* __restrict__ ef,
     const float* __restrict__ ed,
     const float* __restrict__ plw, const float* __restrict__ plb,
     const float* __restrict__ piw, const float* __restrict__ pib,
     const float* __restrict__ fw,  const float* __restrict__ fb,
     const float* __restrict__ tg,  const float* __restrict__ tb,
     const float* __restrict__ ng,  const float* __restrict__ nb,
     const float* __restrict__ ipw, const float* __restrict__ cw,
     const float* __restrict__ cb,  const float* __restrict__ xpw,
     const float* __restrict__ dtw, const float* __restrict__ dtb,
     const float* __restrict__ alog,const float* __restrict__ dp,
     const float* __restrict__ opw,
     const float* __restrict__ w1,  const float* __restrict__ b1,
     const float* __restrict__ w2,  const float* __restrict__ b2,
     float* __restrict__ out)
{
    __shared__ __align__(16) float SMF[SMTOT];
    const int tid  = threadIdx.x;
    const int b    = blockIdx.x >> 3;    // batch group
    const int rank = blockIdx.x & 7;     // CTA rank within group
    unsigned bar_target = 0u;

    // ---------------- featurize + tok LN (4 tokens per rank) -------------
    {
        float* cat = SMF;          // 136
        float* red = SMF + 144;    // 256
        for (int ti = 0; ti < 4; ti++) {
            int tl  = rank*4 + ti;
            int tok = b*TT + tl;
            const float* xr = x + (b*1024 + tl)*5;
            int d = tid;
            if (d < 136) {
                float v;
                if (d < 32)       { int p=(int)xr[0]; p=min(max(p,0),255); v=ep[p*32+d]; }
                else if (d < 64)  { v = xr[1]*plw[d-32] + plb[d-32]; }
                else if (d < 96)  { int f=(int)xr[2]; f=min(max(f,0),63); v=ef[f*32+(d-64)]; }
                else if (d < 128) { v = xr[3]*piw[d-96] + pib[d-96]; }
                else              { int dd=(int)xr[4]; dd=min(max(dd,0),1); v=ed[dd*8+(d-128)]; }
                cat[d] = v;
            }
            __syncthreads();
            float acc = fb[d];
            const float* wrow = fw + d*136;
            #pragma unroll 8
            for (int j = 0; j < 136; j++) acc += cat[j]*wrow[j];
            red[d] = acc; __syncthreads();
            for (int off=128; off; off>>=1){ if (d<off) red[d]+=red[d+off]; __syncthreads(); }
            float mean = red[0]*(1.f/DM); __syncthreads();
            float dv = acc-mean; red[d]=dv*dv; __syncthreads();
            for (int off=128; off; off>>=1){ if (d<off) red[d]+=red[d+off]; __syncthreads(); }
            float var = red[0]*(1.f/DM);
            g_feat[tok*DM + d] = dv*rsqrtf(var+1e-5f)*tg[d] + tb[d];
            __syncthreads();
        }
    }
    bsync(b, bar_target);

    for (int l = 0; l < NL; l++) {
        const float* ipw_l = ipw + (size_t)l*2*DI*DM;
        const float* cw_l  = cw  + (size_t)l*DI*4;
        const float* cb_l  = cb  + (size_t)l*DI;
        const float* xpw_l = xpw + (size_t)l*48*DI;
        const float* dtw_l = dtw + (size_t)l*DI*DR;
        const float* dtb_l = dtb + (size_t)l*DI;
        const float* al_l  = alog+ (size_t)l*DI*DS;
        const float* dp_l  = dp  + (size_t)l*DI;
        const float* opw_l = opw + (size_t)l*DM*DI;

        // -------- in_proj: xz[32,1024] = feat[32,256] @ W^T --------------
        // each rank: 128-col slice, full K=256, BK=32, f32x2 microtile
        {
            float (*As)[36]  = (float(*)[36])SMF;            // 32x36
            float (*Bs)[132] = (float(*)[132])(SMF + 1152);  // 32x132
            const int nb0 = rank*128;
            const float* A = g_feat + (size_t)b*TT*DM;
            int ty = tid >> 5, tx = tid & 31;
            unsigned long long acc2[4][2];
            #pragma unroll
            for (int r = 0; r < 4; r++) { acc2[r][0] = 0ull; acc2[r][1] = 0ull; }
            for (int k0 = 0; k0 < DM; k0 += 32) {
                {   // A: 32x32 = 256 float4, one per thread (cross-CTA -> ldcg)
                    int m = tid >> 3, kq = (tid & 7)*4;
                    float4 av = __ldcg((const float4*)(A + (size_t)m*DM + k0 + kq));
                    As[kq+0][m]=av.x; As[kq+1][m]=av.y; As[kq+2][m]=av.z; As[kq+3][m]=av.w;
                }
                #pragma unroll
                for (int j = 0; j < 4; j++) {   // B (weights): 128x32
                    int i = tid + j*256;
                    int n = i >> 3, kq = (i & 7)*4;
                    float4 bv = *(const float4*)(ipw_l + (size_t)(nb0+n)*DM + k0 + kq);
                    Bs[kq+0][n]=bv.x; Bs[kq+1][n]=bv.y; Bs[kq+2][n]=bv.z; Bs[kq+3][n]=bv.w;
                }
                __syncthreads();
                #pragma unroll
                for (int k = 0; k < 32; k++) {
                    float4 a  = *(const float4*)&As[k][ty*4];
                    float4 bb = *(const float4*)&Bs[k][tx*4];
                    unsigned long long b01 = pk2(bb.x, bb.y);
                    unsigned long long b23 = pk2(bb.z, bb.w);
                    unsigned long long a2;
                    a2 = pk2(a.x, a.x); fma2(acc2[0][0], a2, b01); fma2(acc2[0][1], a2, b23);
                    a2 = pk2(a.y, a.y); fma2(acc2[1][0], a2, b01); fma2(acc2[1][1], a2, b23);
                    a2 = pk2(a.z, a.z); fma2(acc2[2][0], a2, b01); fma2(acc2[2][1], a2, b23);
                    a2 = pk2(a.w, a.w); fma2(acc2[3][0], a2, b01); fma2(acc2[3][1], a2, b23);
                }
                __syncthreads();
            }
            #pragma unroll
            for (int r = 0; r < 4; r++) {
                float2 p = upk2(acc2[r][0]), q = upk2(acc2[r][1]);
                *(float4*)(g_xz + (size_t)(b*TT + ty*4 + r)*(2*DI) + nb0 + tx*4) =
                    make_float4(p.x, p.y, q.x, q.y);
            }
        }
        bsync(b, bar_target);

        // -------- conv+SiLU, x_proj, dt (4 tokens per rank) --------------
        {
            float* xcs  = SMF;        // 512
            float* dbls = SMF + 512;  // 48
            for (int ti = 0; ti < 4; ti++) {
                int tl  = rank*4 + ti;
                int tok = b*TT + tl;
                #pragma unroll
                for (int r = 0; r < 2; r++) {
                    int d = tid + r*256;
                    float acc = cb_l[d];
                    #pragma unroll
                    for (int k = 0; k < 4; k++) {
                        int tt = tl - 3 + k;
                        if (tt >= 0)
                            acc += cw_l[d*4+k] * __ldcg(&g_xz[(size_t)(tok-3+k)*(2*DI) + d]);
                    }
                    xcs[d] = acc / (1.f + __expf(-acc));
                }
                __syncthreads();
                int warp = tid >> 5, lane = tid & 31;
                #pragma unroll
                for (int i = 0; i < 6; i++) {
                    int o = warp*6 + i;
                    const float* wr = xpw_l + o*DI;
                    float p = 0.f;
                    #pragma unroll
                    for (int j = 0; j < 16; j++) p += xcs[j*32+lane]*wr[j*32+lane];
                    #pragma unroll
                    for (int off = 16; off; off >>= 1)
                        p += __shfl_down_sync(0xffffffffu, p, off);
                    if (lane == 0) { dbls[o] = p; g_dbl[tok*48 + o] = p; }
                }
                __syncthreads();
                #pragma unroll
                for (int r = 0; r < 2; r++) {
                    int d = tid + r*256;
                    float v = dtb_l[d];
                    const float* dwr = dtw_l + d*DR;
                    #pragma unroll
                    for (int rr = 0; rr < DR; rr++) v += dbls[rr]*dwr[rr];
                    int tri = (b*DI + d)*TT + tl;
                    g_dtt[tri] = (v > 20.f) ? v : log1pf(__expf(v));
                    g_xct[tri] = xcs[d];
                    g_ztr[tri] = __ldcg(&g_xz[(size_t)tok*(2*DI) + DI + d]);
                }
                __syncthreads();
            }
        }
        bsync(b, bar_target);

        // -------- selective scan: 64 channels per rank -------------------
        {
            float* Bsm = SMF;            // 512
            float* Csm = SMF + 512;      // 512
            float* dts = SMF + 1024;     // 512
            float* ws  = SMF + 1536;     // 512
            float* xs  = SMF + 2048;     // 512
            float* zs  = SMF + 2560;     // 512
            float* es  = SMF + 3072;     // 512
            float* A0s = SMF + 3584;     // 16
            #pragma unroll
            for (int i = tid; i < 512; i += 256) {
                int t = i >> 4, n = i & 15;
                const float* row = g_dbl + (size_t)(b*TT + t)*48;
                Bsm[i] = __ldcg(&row[16+n]);
                Csm[i] = __ldcg(&row[32+n]);
            }
            for (int c = 0; c < 4; c++) {
                int ch0 = rank*64 + c*16;
                __syncthreads();
                if (tid < 16) A0s[tid] = -__expf(al_l[(ch0+tid)*DS]);
                __syncthreads();
                #pragma unroll
                for (int i = tid; i < 512; i += 256) {
                    int ch = i >> 5, t2 = i & 31;
                    int tri = (b*DI + ch0 + ch)*TT + t2;
                    float dtv = __ldcg(&g_dtt[tri]);
                    float xv  = __ldcg(&g_xct[tri]);
                    dts[ch*32+t2] = dtv;
                    ws [ch*32+t2] = dtv*xv;
                    xs [ch*32+t2] = xv;
                    zs [ch*32+t2] = __ldcg(&g_ztr[tri]);
                    es [ch*32+t2] = __expf(dtv * A0s[ch]);
                }
                __syncthreads();
                int ch_l = tid >> 4, n = tid & 15;
                int d = ch0 + ch_l;
                float An = -__expf(al_l[d*DS + n]);
                float A0 = A0s[ch_l];
                bool fast = fabsf(An - (float)(n+1)*A0) <= 1e-5f*fabsf(An) + 1e-7f;
                fast = __all_sync(0xffffffffu, fast);
                float Dd = dp_l[d];
                float h = 0.f;
                int np = n + 1;
                if (fast) {
                    #pragma unroll 4
                    for (int t = 0; t < TT; t++) {
                        float e1 = es[ch_l*32+t];
                        float p2 = e1*e1, p4 = p2*p2, p8 = p4*p4;
                        float a = 1.f;
                        if (np & 1)  a *= e1;
                        if (np & 2)  a *= p2;
                        if (np & 4)  a *= p4;
                        if (np & 8)  a *= p8;
                        if (np & 16) a *= p8*p8;
                        h = a*h + ws[ch_l*32+t]*Bsm[t*16+n];
                        float v = h*Csm[t*16+n];
                        v += __shfl_xor_sync(0xffffffffu, v, 8);
                        v += __shfl_xor_sync(0xffffffffu, v, 4);
                        v += __shfl_xor_sync(0xffffffffu, v, 2);
                        v += __shfl_xor_sync(0xffffffffu, v, 1);
                        if (n == 0) {
                            float zv = zs[ch_l*32+t];
                            float sz = zv / (1.f + __expf(-zv));
                            g_y[(size_t)(b*TT+t)*DI + d] = (v + Dd*xs[ch_l*32+t]) * sz;
                        }
                    }
                } else {
                    #pragma unroll 4
                    for (int t = 0; t < TT; t++) {
                        float a = __expf(dts[ch_l*32+t]*An);
                        h = a*h + ws[ch_l*32+t]*Bsm[t*16+n];
                        float v = h*Csm[t*16+n];
                        v += __shfl_xor_sync(0xffffffffu, v, 8);
                        v += __shfl_xor_sync(0xffffffffu, v, 4);
                        v += __shfl_xor_sync(0xffffffffu, v, 2);
                        v += __shfl_xor_sync(0xffffffffu, v, 1);
                        if (n == 0) {
                            float zv = zs[ch_l*32+t];
                            float sz = zv / (1.f + __expf(-zv));
                            g_y[(size_t)(b*TT+t)*DI + d] = (v + Dd*xs[ch_l*32+t]) * sz;
                        }
                    }
                }
            }
        }
        bsync(b, bar_target);

        // -------- out_proj: rank -> (64-col slice, half-K) partials ------
        {
            float (*As)[36] = (float(*)[36])SMF;            // 32x36
            float (*Bs)[68] = (float(*)[68])(SMF + 1152);   // 32x68
            const int nsl = (rank & 3)*64;
            const int kh  = rank >> 2;           // 0/1 -> K half
            const int kb  = kh*256;
            int ty = tid >> 5, tx = tid & 31;
            float acc[4][2] = {};
            for (int k0 = 0; k0 < 256; k0 += 32) {
                {   // A: y rows 32 x 32k (cross-CTA -> ldcg)
                    int m = tid >> 3, kq = (tid & 7)*4;
                    float4 av = __ldcg((const float4*)(g_y + (size_t)(b*TT+m)*DI + kb + k0 + kq));
                    As[kq+0][m]=av.x; As[kq+1][m]=av.y; As[kq+2][m]=av.z; As[kq+3][m]=av.w;
                }
                #pragma unroll
                for (int j = 0; j < 2; j++) {   // B (weights): 64x32
                    int i = tid + j*256;
                    int n = i >> 3, kq = (i & 7)*4;
                    float4 bv = *(const float4*)(opw_l + (size_t)(nsl+n)*DI + kb + k0 + kq);
                    Bs[kq+0][n]=bv.x; Bs[kq+1][n]=bv.y; Bs[kq+2][n]=bv.z; Bs[kq+3][n]=bv.w;
                }
                __syncthreads();
                #pragma unroll
                for (int k = 0; k < 32; k++) {
                    float4 a  = *(const float4*)&As[k][ty*4];
                    float2 bb = *(const float2*)&Bs[k][tx*2];
                    float ar[4] = {a.x,a.y,a.z,a.w};
                    #pragma unroll
                    for (int r = 0; r < 4; r++) {
                        acc[r][0] += ar[r]*bb.x;
                        acc[r][1] += ar[r]*bb.y;
                    }
                }
                __syncthreads();
            }
            #pragma unroll
            for (int r = 0; r < 4; r++)
                *(float2*)(&g_outp[kh][(size_t)(b*TT + ty*4 + r)*DM + nsl + tx*2]) =
                    make_float2(acc[r][0], acc[r][1]);
        }
        bsync(b, bar_target);

        // -------- residual + LN -> feat (4 tokens per rank) --------------
        {
            float* red = SMF;
            for (int ti = 0; ti < 4; ti++) {
                int tok = b*TT + rank*4 + ti;
                int d = tid;
                size_t o = (size_t)tok*DM + d;
                float v = g_feat[o] + __ldcg(&g_outp[0][o]) + __ldcg(&g_outp[1][o]);
                red[d] = v; __syncthreads();
                for (int off=128; off; off>>=1){ if (d<off) red[d]+=red[d+off]; __syncthreads(); }
                float mean = red[0]*(1.f/DM); __syncthreads();
                float dv = v-mean; red[d]=dv*dv; __syncthreads();
                for (int off=128; off; off>>=1){ if (d<off) red[d]+=red[d+off]; __syncthreads(); }
                float var = red[0]*(1.f/DM);
                g_feat[o] = dv*rsqrtf(var+1e-5f)*ng[d] + nb[d];
                __syncthreads();
            }
        }
        bsync(b, bar_target);
    }

    // barrier bookkeeping reset (safe: last finisher resets; no more arrivals)
    if (tid == 0) {
        if (atomicAdd(&g_fin[b*BSTRIDE], 1u) == CSZ-1) {
            atomicExch(&g_cnt[b*BSTRIDE], 0u);
            atomicExch(&g_fin[b*BSTRIDE], 0u);
        }
    }

    // ---------------- classifier on token 31 (rank 0 per group) ----------
    if (rank == 0) {
        float* hs = SMF;
        int j = tid;
        const float* fr = g_feat + (size_t)(b*TT + 31)*DM;
        if (j < 128) {
            float acc = b1[j];
            const float* wr = w1 + j*DM;
            #pragma unroll 8
            for (int d = 0; d < DM; d++) acc += __ldcg(&fr[d])*wr[d];
            hs[j] = fmaxf(acc, 0.f);
        }
        __syncthreads();
        if (j < 2) {
            float o = b2[j];
            const float* w2r = w2 + j*128;
            #pragma unroll 8
            for (int k = 0; k < 128; k++) o += hs[k]*w2r[k];
            out[b*2 + j] = o;
        }
    }
}

// ---------------------------------------------------------------------------
extern "C" void kernel_launch(void* const* d_in, const int* in_sizes, int n_in,
                              void* d_out, int out_size)
{
    mega<<<NB*CSZ, THREADS>>>(
        (const float*)d_in[0],  (const float*)d_in[1],  (const float*)d_in[2],
        (const float*)d_in[3],  (const float*)d_in[4],  (const float*)d_in[5],
        (const float*)d_in[6],  (const float*)d_in[7],  (const float*)d_in[8],
        (const float*)d_in[9],  (const float*)d_in[10], (const float*)d_in[11],
        (const float*)d_in[12], (const float*)d_in[13], (const float*)d_in[14],
        (const float*)d_in[15], (const float*)d_in[16], (const float*)d_in[17],
        (const float*)d_in[18], (const float*)d_in[19], (const float*)d_in[20],
        (const float*)d_in[21], (const float*)d_in[22], (const float*)d_in[23],
        (const float*)d_in[24], (const float*)d_in[25], (const float*)d_in[26],
        (float*)d_out);
}

// round 7
// speedup vs baseline: 1.5771x; 1.2262x over previous
#include <cuda_runtime.h>
#include <cuda_bf16.h>
#include <math.h>

// B=16, T=32 (early exit: only token 31 used; all ops causal), DM=256,
// DI=512, DS=16, DR=16, DCONV=4, L=4. One persistent megakernel, grid-wide
// stages; barrier = atomic arrival + plain-load polling (no atomic spin).

#define NB      16
#define TT      32
#define NTOK    (NB*TT)      // 512
#define DM      256
#define DI      512
#define DS      16
#define DR      16
#define NL      4
#define THREADS 256
#define SPLIT_IN  2
#define SPLIT_OUT 4

// scratch (device globals; no allocation allowed)
__device__ __align__(16) float g_feat[NTOK*DM];
__device__ __align__(16) float g_xzp [SPLIT_IN][NTOK*2*DI];
__device__ __align__(16) float g_dbl [NTOK*48];
__device__ __align__(16) float g_xct [NB*DI*TT];
__device__ __align__(16) float g_ztr [NB*DI*TT];
__device__ __align__(16) float g_dtt [NB*DI*TT];
__device__ __align__(16) float g_y   [NTOK*DI];
__device__ __align__(16) float g_outp[SPLIT_OUT][NTOK*DM];

__device__ unsigned          g_cnt;
__device__ volatile unsigned g_rel;

__global__ void reset_bar() { g_cnt = 0u; g_rel = 0u; }

// fast grid barrier: one atomic arrival per block; waiters poll with LDG
__device__ __forceinline__ void gsync(unsigned& gen) {
    __syncthreads();
    if (threadIdx.x == 0) {
        gen += 1u;
        __threadfence();
        unsigned a = atomicAdd(&g_cnt, 1u) + 1u;
        if (a == gen * gridDim.x) {
            __threadfence();
            g_rel = gen;                       // release store
        } else {
            while (g_rel < gen) { }            // plain-load poll (L2 shared)
        }
        __threadfence();
    }
    __syncthreads();
}

#define SMTOT 3664

// ---------------------------------------------------------------------------
// 64x64 tile SGEMM piece: C[bm:bm+64, bn:bn+64] = A[.,kbeg:kend] @ B^T
// A = activations (ldcg), B = weights (ldca).
// ---------------------------------------------------------------------------
__device__ __forceinline__ void gemm_tile(const float* __restrict__ A,
                                          const float* __restrict__ B,
                                          float* __restrict__ C,
                                          int N, int K, int bm, int bn,
                                          int kbeg, int kend, float* sm)
{
    float (*As)[68] = (float(*)[68])sm;
    float (*Bs)[68] = (float(*)[68])(sm + 16*68);
    int tid = threadIdx.x;
    int lr = tid >> 2, lk = (tid & 3) * 4;
    int ty = tid >> 4, tx = tid & 15;
    float acc[4][4] = {};
    for (int k0 = kbeg; k0 < kend; k0 += 16) {
        float4 av = __ldcg((const float4*)(A + (size_t)(bm+lr)*K + k0 + lk));
        float4 bv = *(const float4*)(B + (size_t)(bn+lr)*K + k0 + lk);
        As[lk+0][lr]=av.x; As[lk+1][lr]=av.y; As[lk+2][lr]=av.z; As[lk+3][lr]=av.w;
        Bs[lk+0][lr]=bv.x; Bs[lk+1][lr]=bv.y; Bs[lk+2][lr]=bv.z; Bs[lk+3][lr]=bv.w;
        __syncthreads();
        #pragma unroll
        for (int k = 0; k < 16; k++) {
            float4 a  = *(const float4*)&As[k][ty*4];
            float4 bb = *(const float4*)&Bs[k][tx*4];
            float ar[4] = {a.x,a.y,a.z,a.w};
            float br[4] = {bb.x,bb.y,bb.z,bb.w};
            #pragma unroll
            for (int r = 0; r < 4; r++)
                #pragma unroll
                for (int c = 0; c < 4; c++)
                    acc[r][c] += ar[r]*br[c];
        }
        __syncthreads();
    }
    #pragma unroll
    for (int r = 0; r < 4; r++)
        *(float4*)(C + (size_t)(bm+ty*4+r)*N + bn + tx*4) =
            make_float4(acc[r][0],acc[r][1],acc[r][2],acc[r][3]);
}

__device__ __forceinline__ void stage_gemm(const float* A, const float* W,
                                           float* Cp, int M, int N, int K,
                                           int S, float* sm)
{
    int ntn = N/64, nt = (M/64)*ntn;
    int ks = K / S;
    for (int w = blockIdx.x; w < nt*S; w += gridDim.x) {
        int s = w / nt, t = w - s*nt;
        int bm = (t / ntn)*64, bn = (t - (t/ntn)*ntn)*64;
        gemm_tile(A, W, Cp + (size_t)s*M*N, N, K, bm, bn, s*ks, s*ks+ks, sm);
    }
}

// ---------------------------------------------------------------------------
__global__ void __launch_bounds__(THREADS, 2)
mega(const float* __restrict__ x,
     const float* __restrict__ ep,  const float* __restrict__ ef,
     const float* __restrict__ ed,
     const float* __restrict__ plw, const float* __restrict__ plb,
     const float* __restrict__ piw, const float* __restrict__ pib,
     const float* __restrict__ fw,  const float* __restrict__ fb,
     const float* __restrict__ tg,  const float* __restrict__ tb,
     const float* __restrict__ ng,  const float* __restrict__ nb,
     const float* __restrict__ ipw, const float* __restrict__ cw,
     const float* __restrict__ cb,  const float* __restrict__ xpw,
     const float* __restrict__ dtw, const float* __restrict__ dtb,
     const float* __restrict__ alog,const float* __restrict__ dp,
     const float* __restrict__ opw,
     const float* __restrict__ w1,  const float* __restrict__ b1,
     const float* __restrict__ w2,  const float* __restrict__ b2,
     float* __restrict__ out)
{
    __shared__ __align__(16) float SMF[SMTOT];
    unsigned gen = 0u;
    const int tid = threadIdx.x;
    const int G = gridDim.x;

    // ---------------- featurize + tok LN -> g_feat -----------------------
    {
        float* cat = SMF;          // 136
        float* red = SMF + 144;    // 256
        for (int tok = blockIdx.x; tok < NTOK; tok += G) {
            int b = tok >> 5, tl = tok & 31;
            const float* xr = x + (b*1024 + tl)*5;
            int d = tid;
            if (d < 136) {
                float v;
                if (d < 32)       { int p=(int)xr[0]; p=min(max(p,0),255); v=ep[p*32+d]; }
                else if (d < 64)  { v = xr[1]*plw[d-32] + plb[d-32]; }
                else if (d < 96)  { int f=(int)xr[2]; f=min(max(f,0),63); v=ef[f*32+(d-64)]; }
                else if (d < 128) { v = xr[3]*piw[d-96] + pib[d-96]; }
                else              { int dd=(int)xr[4]; dd=min(max(dd,0),1); v=ed[dd*8+(d-128)]; }
                cat[d] = v;
            }
            __syncthreads();
            float acc = fb[d];
            const float* wrow = fw + d*136;
            #pragma unroll 8
            for (int j = 0; j < 136; j++) acc += cat[j]*wrow[j];
            red[d] = acc; __syncthreads();
            for (int off=128; off; off>>=1){ if (d<off) red[d]+=red[d+off]; __syncthreads(); }
            float mean = red[0]*(1.f/DM); __syncthreads();
            float dv = acc-mean; red[d]=dv*dv; __syncthreads();
            for (int off=128; off; off>>=1){ if (d<off) red[d]+=red[d+off]; __syncthreads(); }
            float var = red[0]*(1.f/DM);
            g_feat[tok*DM + d] = dv*rsqrtf(var+1e-5f)*tg[d] + tb[d];
            __syncthreads();
        }
    }
    gsync(gen);

    for (int l = 0; l < NL; l++) {
        const float* ipw_l = ipw + (size_t)l*2*DI*DM;
        const float* cw_l  = cw  + (size_t)l*DI*4;
        const float* cb_l  = cb  + (size_t)l*DI;
        const float* xpw_l = xpw + (size_t)l*48*DI;
        const float* dtw_l = dtw + (size_t)l*DI*DR;
        const float* dtb_l = dtb + (size_t)l*DI;
        const float* al_l  = alog+ (size_t)l*DI*DS;
        const float* dp_l  = dp  + (size_t)l*DI;
        const float* opw_l = opw + (size_t)l*DM*DI;

        // -------- in_proj: xz = feat @ ipw^T (split-K=2 partials) --------
        stage_gemm(g_feat, ipw_l, &g_xzp[0][0], NTOK, 2*DI, DM, SPLIT_IN, SMF);
        gsync(gen);

        // -------- conv+SiLU, x_proj, dt (per token) ----------------------
        {
            float* xcs  = SMF;        // 512
            float* dbls = SMF + 512;  // 48
            const float* xz0 = &g_xzp[0][0];
            const float* xz1 = &g_xzp[1][0];
            for (int tok = blockIdx.x; tok < NTOK; tok += G) {
                int b = tok >> 5, tl = tok & 31;
                #pragma unroll
                for (int r = 0; r < 2; r++) {
                    int d = tid + r*256;
                    float acc = cb_l[d];
                    #pragma unroll
                    for (int k = 0; k < 4; k++) {
                        int tt = tl - 3 + k;
                        if (tt >= 0) {
                            int off = (tok-3+k)*(2*DI) + d;
                            acc += cw_l[d*4+k] * (__ldcg(&xz0[off]) + __ldcg(&xz1[off]));
                        }
                    }
                    xcs[d] = acc / (1.f + __expf(-acc));
                }
                __syncthreads();
                int warp = tid >> 5, lane = tid & 31;
                #pragma unroll
                for (int i = 0; i < 6; i++) {
                    int o = warp*6 + i;
                    const float* wr = xpw_l + o*DI;
                    float p = 0.f;
                    #pragma unroll
                    for (int j = 0; j < 16; j++) p += xcs[j*32+lane]*wr[j*32+lane];
                    #pragma unroll
                    for (int off = 16; off; off >>= 1)
                        p += __shfl_down_sync(0xffffffffu, p, off);
                    if (lane == 0) { dbls[o] = p; g_dbl[tok*48 + o] = p; }
                }
                __syncthreads();
                #pragma unroll
                for (int r = 0; r < 2; r++) {
                    int d = tid + r*256;
                    float v = dtb_l[d];
                    const float* dwr = dtw_l + d*DR;
                    #pragma unroll
                    for (int rr = 0; rr < DR; rr++) v += dbls[rr]*dwr[rr];
                    int tri = (b*DI + d)*TT + tl;
                    g_dtt[tri] = (v > 20.f) ? v : log1pf(__expf(v));
                    g_xct[tri] = xcs[d];
                    int zo = tok*2*DI + DI + d;
                    g_ztr[tri] = __ldcg(&xz0[zo]) + __ldcg(&xz1[zo]);
                }
                __syncthreads();
            }
        }
        gsync(gen);

        // -------- selective scan: serial t, parallel (d,n) ---------------
        {
            float* Bsm = SMF;            // 512
            float* Csm = SMF + 512;      // 512
            float* ws  = SMF + 1024;     // 512
            float* es  = SMF + 1536;     // 512
            float* xs  = SMF + 2048;     // 512
            float* zs  = SMF + 2560;     // 512
            float* dts = SMF + 3072;     // 512
            float* A0s = SMF + 3584;     // 16
            for (int chunk = blockIdx.x; chunk < NB*32; chunk += G) {
                int b = chunk >> 5;
                int d0 = (chunk & 31) * 16;
                if (tid < 16) A0s[tid] = -__expf(al_l[(d0+tid)*DS]);
                __syncthreads();
                #pragma unroll
                for (int i = tid; i < 512; i += 256) {
                    int t = i >> 4, n = i & 15;
                    const float* row = g_dbl + (b*TT + t)*48;
                    Bsm[t*16+n] = __ldcg(&row[16+n]);
                    Csm[t*16+n] = __ldcg(&row[32+n]);
                    int ch = i >> 5, tt = i & 31;
                    int tri = (b*DI + d0 + ch)*TT + tt;
                    float dtv = __ldcg(&g_dtt[tri]);
                    float xv  = __ldcg(&g_xct[tri]);
                    dts[ch*32+tt] = dtv;
                    ws [ch*32+tt] = dtv*xv;
                    xs [ch*32+tt] = xv;
                    zs [ch*32+tt] = __ldcg(&g_ztr[tri]);
                    es [ch*32+tt] = __expf(dtv * A0s[ch]);
                }
                __syncthreads();
                int lane = tid & 31;
                int ch = (tid >> 5)*2 + (lane >> 4);
                int n = lane & 15;
                int d = d0 + ch;
                float An = -__expf(al_l[d*DS + n]);
                float A0 = A0s[ch];
                bool fast = fabsf(An - (float)(n+1)*A0) <= 1e-5f*fabsf(An) + 1e-7f;
                fast = __all_sync(0xffffffffu, fast);
                float Dd = dp_l[d];
                float h = 0.f;
                int np = n + 1;
                if (fast) {
                    #pragma unroll 4
                    for (int t = 0; t < TT; t++) {
                        float e1 = es[ch*32+t];
                        float p2 = e1*e1, p4 = p2*p2, p8 = p4*p4;
                        float a = 1.f;
                        if (np & 1)  a *= e1;
                        if (np & 2)  a *= p2;
                        if (np & 4)  a *= p4;
                        if (np & 8)  a *= p8;
                        if (np & 16) a *= p8*p8;
                        h = a*h + ws[ch*32+t]*Bsm[t*16+n];
                        float v = h*Csm[t*16+n];
                        v += __shfl_xor_sync(0xffffffffu, v, 8);
                        v += __shfl_xor_sync(0xffffffffu, v, 4);
                        v += __shfl_xor_sync(0xffffffffu, v, 2);
                        v += __shfl_xor_sync(0xffffffffu, v, 1);
                        if (n == 0) {
                            float zv = zs[ch*32+t];
                            float sz = zv / (1.f + __expf(-zv));
                            g_y[(b*TT+t)*DI + d] = (v + Dd*xs[ch*32+t]) * sz;
                        }
                    }
                } else {
                    #pragma unroll 4
                    for (int t = 0; t < TT; t++) {
                        float a = __expf(dts[ch*32+t]*An);
                        h = a*h + ws[ch*32+t]*Bsm[t*16+n];
                        float v = h*Csm[t*16+n];
                        v += __shfl_xor_sync(0xffffffffu, v, 8);
                        v += __shfl_xor_sync(0xffffffffu, v, 4);
                        v += __shfl_xor_sync(0xffffffffu, v, 2);
                        v += __shfl_xor_sync(0xffffffffu, v, 1);
                        if (n == 0) {
                            float zv = zs[ch*32+t];
                            float sz = zv / (1.f + __expf(-zv));
                            g_y[(b*TT+t)*DI + d] = (v + Dd*xs[ch*32+t]) * sz;
                        }
                    }
                }
                __syncthreads();
            }
        }
        gsync(gen);

        // -------- out_proj: split-K=4 partials ---------------------------
        stage_gemm(g_y, opw_l, &g_outp[0][0], NTOK, DM, DI, SPLIT_OUT, SMF);
        gsync(gen);

        // -------- residual + LN -> feat ----------------------------------
        {
            float* red = SMF;
            for (int tok = blockIdx.x; tok < NTOK; tok += G) {
                int d = tid;
                int o = tok*DM + d;
                float v = __ldcg(&g_feat[o]) + __ldcg(&g_outp[0][o]) + __ldcg(&g_outp[1][o])
                        + __ldcg(&g_outp[2][o]) + __ldcg(&g_outp[3][o]);
                red[d] = v; __syncthreads();
                for (int off=128; off; off>>=1){ if (d<off) red[d]+=red[d+off]; __syncthreads(); }
                float mean = red[0]*(1.f/DM); __syncthreads();
                float dv = v-mean; red[d]=dv*dv; __syncthreads();
                for (int off=128; off; off>>=1){ if (d<off) red[d]+=red[d+off]; __syncthreads(); }
                float var = red[0]*(1.f/DM);
                g_feat[o] = dv*rsqrtf(var+1e-5f)*ng[d] + nb[d];
                __syncthreads();
            }
        }
        gsync(gen);
    }

    // ---------------- classifier on token 31 ------------------------------
    if (blockIdx.x < NB) {
        float* hs = SMF;
        int b = blockIdx.x, j = tid;
        const float* fr = g_feat + (b*TT + 31)*DM;
        if (j < 128) {
            float acc = b1[j];
            const float* wr = w1 + j*DM;
            #pragma unroll 8
            for (int d = 0; d < DM; d++) acc += __ldcg(&fr[d])*wr[d];
            hs[j] = fmaxf(acc, 0.f);
        }
        __syncthreads();
        if (j < 2) {
            float o = b2[j];
            const float* w2r = w2 + j*128;
            #pragma unroll 8
            for (int k = 0; k < 128; k++) o += hs[k]*w2r[k];
            out[b*2 + j] = o;
        }
    }
}

// ---------------------------------------------------------------------------
extern "C" void kernel_launch(void* const* d_in, const int* in_sizes, int n_in,
                              void* d_out, int out_size)
{
    static int G = 0;
    if (!G) {
        int dev = 0; cudaGetDevice(&dev);
        int nsm = 0; cudaDeviceGetAttribute(&nsm, cudaDevAttrMultiProcessorCount, dev);
        int bpm = 0;
        cudaOccupancyMaxActiveBlocksPerMultiprocessor(&bpm, mega, THREADS, 0);
        if (bpm < 1) bpm = 1;
        if (bpm > 2) bpm = 2;
        G = nsm * bpm;
        if (G < 1) G = 1;
        if (G > 1024) G = 1024;
    }

    reset_bar<<<1,1>>>();
    mega<<<G, THREADS>>>(
        (const float*)d_in[0],  (const float*)d_in[1],  (const float*)d_in[2],
        (const float*)d_in[3],  (const float*)d_in[4],  (const float*)d_in[5],
        (const float*)d_in[6],  (const float*)d_in[7],  (const float*)d_in[8],
        (const float*)d_in[9],  (const float*)d_in[10], (const float*)d_in[11],
        (const float*)d_in[12], (const float*)d_in[13], (const float*)d_in[14],
        (const float*)d_in[15], (const float*)d_in[16], (const float*)d_in[17],
        (const float*)d_in[18], (const float*)d_in[19], (const float*)d_in[20],
        (const float*)d_in[21], (const float*)d_in[22], (const float*)d_in[23],
        (const float*)d_in[24], (const float*)d_in[25], (const float*)d_in[26],
        (float*)d_out);
}